// round 6
// baseline (speedup 1.0000x reference)
#include <cuda_runtime.h>
#include <cstdint>

#define HID    128
#define BATCH  16
#define TSTEPS 8640            // 30*24*12
#define CL     8               // CTAs per cluster (one cluster per batch element)
#define UNITS  16              // hidden units owned per CTA (HID / CL)
#define NT     256             // threads per CTA (8 warps)

// ---------------- PTX helpers ----------------
__device__ __forceinline__ uint32_t s2u(const void* p) {
    return (uint32_t)__cvta_generic_to_shared(p);
}
__device__ __forceinline__ uint32_t mapa_rank(uint32_t a, uint32_t r) {
    uint32_t d;
    asm("mapa.shared::cluster.u32 %0, %1, %2;" : "=r"(d) : "r"(a), "r"(r));
    return d;
}
// fused remote store + tx-completion on the remote CTA's mbarrier
__device__ __forceinline__ void st_async64(uint32_t addr, uint64_t v, uint32_t mbar) {
    asm volatile(
        "st.async.shared::cluster.mbarrier::complete_tx::bytes.b64 [%0], %1, [%2];"
        :: "r"(addr), "l"(v), "r"(mbar) : "memory");
}
__device__ __forceinline__ void mbar_expect_tx(uint32_t bar, uint32_t bytes) {
    asm volatile("mbarrier.arrive.expect_tx.shared.b64 _, [%0], %1;"
                 :: "r"(bar), "r"(bytes) : "memory");
}
__device__ __forceinline__ void mbar_wait_parity(uint32_t bar, uint32_t parity) {
    uint32_t done;
    asm volatile(
        "{\n\t.reg .pred p;\n\t"
        "mbarrier.try_wait.parity.acquire.cluster.shared::cta.b64 p, [%1], %2;\n\t"
        "selp.b32 %0, 1, 0, p;\n\t}"
        : "=r"(done) : "r"(bar), "r"(parity) : "memory");
    while (!done) {
        asm volatile(
            "{\n\t.reg .pred p;\n\t"
            "mbarrier.try_wait.parity.acquire.cluster.shared::cta.b64 p, [%1], %2, 0x989680;\n\t"
            "selp.b32 %0, 1, 0, p;\n\t}"
            : "=r"(done) : "r"(bar), "r"(parity) : "memory");
    }
}
// named barriers: id2/id3 — warp 0 consumes (bar.sync), warps 1-7 produce (bar.arrive)
__device__ __forceinline__ void bar_sync(int id, int cnt) {
    asm volatile("bar.sync %0, %1;" :: "r"(id), "r"(cnt) : "memory");
}
__device__ __forceinline__ void bar_arrive(int id, int cnt) {
    asm volatile("bar.arrive %0, %1;" :: "r"(id), "r"(cnt) : "memory");
}

__device__ __forceinline__ float sigf(float x) {
    return __fdividef(1.0f, 1.0f + __expf(-x));
}
__device__ __forceinline__ float tanh_f(float x) {
    float e = __expf(2.0f * x);
    return 1.0f - __fdividef(2.0f, e + 1.0f);
}

// packed f32x2 fma (sm_103a FFMA2)
__device__ __forceinline__ uint64_t fma2(uint64_t a, uint64_t b, uint64_t c) {
    uint64_t d;
    asm("fma.rn.f32x2 %0, %1, %2, %3;" : "=l"(d) : "l"(a), "l"(b), "l"(c));
    return d;
}
// 32-column dot: 16 packed FMAs over 4 chains
__device__ __forceinline__ float dot32p(const uint64_t* __restrict__ wp,
                                        const float* __restrict__ h) {
    const ulonglong2* hp = reinterpret_cast<const ulonglong2*>(h);
    uint64_t a0 = 0ull, a1 = 0ull, a2 = 0ull, a3 = 0ull;
#pragma unroll
    for (int k = 0; k < 4; k++) {
        ulonglong2 va = hp[2 * k];
        ulonglong2 vb = hp[2 * k + 1];
        a0 = fma2(wp[4 * k + 0], va.x, a0);
        a1 = fma2(wp[4 * k + 1], va.y, a1);
        a2 = fma2(wp[4 * k + 2], vb.x, a2);
        a3 = fma2(wp[4 * k + 3], vb.y, a3);
    }
    uint64_t s01, s23, sall;
    asm("add.rn.f32x2 %0, %1, %2;" : "=l"(s01)  : "l"(a0),  "l"(a1));
    asm("add.rn.f32x2 %0, %1, %2;" : "=l"(s23)  : "l"(a2),  "l"(a3));
    asm("add.rn.f32x2 %0, %1, %2;" : "=l"(sall) : "l"(s01), "l"(s23));
    return __uint_as_float((uint32_t)sall) + __uint_as_float((uint32_t)(sall >> 32));
}
__device__ __forceinline__ float hsum4(float4 v) {
    return (v.x + v.y) + (v.z + v.w);
}

// ---------------- kernel ----------------
extern "C" __global__ void __launch_bounds__(NT, 1) __cluster_dims__(CL, 1, 1)
lstm_decoder_kernel(const float* __restrict__ y0,
                    const float* __restrict__ h0g,
                    const float* __restrict__ c0g,
                    const float* __restrict__ Wi0,
                    const float* __restrict__ Wh0,
                    const float* __restrict__ bi0,
                    const float* __restrict__ bh0,
                    const float* __restrict__ Wi1,
                    const float* __restrict__ Wh1,
                    const float* __restrict__ bi1,
                    const float* __restrict__ bh1,
                    const float* __restrict__ fcw,
                    const float* __restrict__ fcbp,
                    float* __restrict__ out)
{
    __shared__ __align__(16) float bufH0[2][HID];     // double-buffered layer-0 h
    __shared__ __align__(16) float bufH1[2][HID];     // double-buffered layer-1 h
    __shared__ __align__(16) float part_s[NT];        // layer-0 partials (transposed)
    __shared__ __align__(16) float part2_s[NT];       // layer-1 partials (transposed)
    __shared__ __align__(16) uint64_t barH0[2], barH1[2];  // double-buffered mbarriers

    const int t     = threadIdx.x;
    const int batch = blockIdx.x >> 3;
    const int rank  = blockIdx.x & 7;

    const int chunk = t >> 6;                          // 32-col slice 0..3
    const int r     = t & 63;                          // gate row 0..63 (local)
    const int gb    = r >> 4;                          // 0=i,1=f,2=g,3=o
    const int jl    = r & 15;                          // local hidden unit
    const int R     = gb * 128 + rank * UNITS + jl;    // global gate row
    const int cbase = chunk * 32;
    const int tp    = r * 4 + chunk;                   // transposed partial index

    const float fb   = fcbp[0];
    const float wi0R = Wi0[R];                         // input weight of this gate row

    // -------- load + pack weights (one-time) --------
    // w0p: Wh0 row slice; wAp: Wi1 row slice; wBp: Wh1 row slice;
    // wCp: folded fc weights  (wi0_R * fcw slice)  -- carries y = fc(h1) into layer-0 gates
    uint64_t w0p[16], wAp[16], wBp[16], wCp[16];
    {
        const ulonglong2* p0 = reinterpret_cast<const ulonglong2*>(Wh0 + R * HID + cbase);
        const ulonglong2* pA = reinterpret_cast<const ulonglong2*>(Wi1 + R * HID + cbase);
        const ulonglong2* pB = reinterpret_cast<const ulonglong2*>(Wh1 + R * HID + cbase);
#pragma unroll
        for (int k = 0; k < 8; k++) {
            ulonglong2 v0 = p0[k], vA = pA[k], vB = pB[k];
            w0p[2 * k] = v0.x; w0p[2 * k + 1] = v0.y;
            wAp[2 * k] = vA.x; wAp[2 * k + 1] = vA.y;
            wBp[2 * k] = vB.x; wBp[2 * k + 1] = vB.y;
        }
#pragma unroll
        for (int k = 0; k < 16; k++) {
            float c0 = wi0R * fcw[cbase + 2 * k];
            float c1 = wi0R * fcw[cbase + 2 * k + 1];
            wCp[k] = ((uint64_t)__float_as_uint(c1) << 32) | (uint64_t)__float_as_uint(c0);
        }
    }
    // nonlin-lane constants (warp 0, lanes < 16): per-gate effective bias
    //   b0* includes + wi0 * fcb  (fc bias folded into layer-0 gate bias)
    float b0i = 0.f, b0f = 0.f, b0g = 0.f, b0o = 0.f;
    float b1i = 0.f, b1f = 0.f, b1g = 0.f, b1o = 0.f;
    if (t < UNITS) {
        const int u = rank * UNITS + t;
        b0i = bi0[u]       + bh0[u]       + Wi0[u]       * fb;
        b0f = bi0[128 + u] + bh0[128 + u] + Wi0[128 + u] * fb;
        b0g = bi0[256 + u] + bh0[256 + u] + Wi0[256 + u] * fb;
        b0o = bi0[384 + u] + bh0[384 + u] + Wi0[384 + u] * fb;
        b1i = bi1[u]       + bh1[u];
        b1f = bi1[128 + u] + bh1[128 + u];
        b1g = bi1[256 + u] + bh1[256 + u];
        b1o = bi1[384 + u] + bh1[384 + u];
    }
    // fc output weights (warp 1 lanes) -- output path only, off critical path
    float fw0 = 0.f, fw1 = 0.f, fw2 = 0.f, fw3 = 0.f;
    if (t >= 32 && t < 64) {
        const int l = t - 32;
        fw0 = fcw[l]; fw1 = fcw[32 + l]; fw2 = fcw[64 + l]; fw3 = fcw[96 + l];
    }

    // -------- initial state --------
    if (t < HID) {
        bufH0[0][t] = h0g[batch * HID + t];
        bufH1[0][t] = h0g[BATCH * HID + batch * HID + t];
    }
    float c0v = 0.f, c1v = 0.f;
    if (t < UNITS) {
        c0v = c0g[batch * HID + rank * UNITS + t];
        c1v = c0g[BATCH * HID + batch * HID + rank * UNITS + t];
    }
    const float y0v = y0[batch];
    if (t == 0) {
#pragma unroll
        for (int b = 0; b < 2; b++) {
            asm volatile("mbarrier.init.shared.b64 [%0], 1;" :: "r"(s2u(&barH0[b])) : "memory");
            asm volatile("mbarrier.init.shared.b64 [%0], 1;" :: "r"(s2u(&barH1[b])) : "memory");
        }
    }
    __syncthreads();
    asm volatile("barrier.cluster.arrive.aligned;" ::: "memory");
    asm volatile("barrier.cluster.wait.aligned;" ::: "memory");

    // -------- precompute DSMEM peer addresses --------
    const uint32_t barH0a = s2u(&barH0[0]);            // +8*sel selects buffer
    const uint32_t barH1a = s2u(&barH1[0]);
    const uint32_t h0base = s2u(&bufH0[0][0]);
    const uint32_t dH1    = s2u(&bufH1[0][0]) - h0base;
    uint32_t pbase[CL], pb0[CL], pb1[CL];
#pragma unroll
    for (int c = 0; c < CL; c++) {
        pbase[c] = mapa_rank(h0base, c);
        pb0[c]   = mapa_rank(barH0a, c);
        pb1[c]   = mapa_rank(barH1a, c);
    }

    float* outp = out + batch * TSTEPS;

    // -------- prologue: layer-0 partials for step 0 --------
    // step 0 uses the true y0 input:  add  wi0_R*(y0 - fcb)  so that the
    // reduce's folded +wi0*fcb yields exactly wi0*y0.
    {
        float p = dot32p(w0p, &bufH0[0][cbase]);
        if (chunk == 0) p += wi0R * (y0v - fb);
        part_s[tp] = p;
    }
    __syncthreads();

    // ================= main recurrence =================
    // Entering iter s (cur=s&1): h0_s in bufH0[cur], h1_s in bufH1[cur],
    //   part_s = transposed (Wh0@h0_s + wi0 (x) fcw @ h1_s) partials.
    for (int s = 0; s < TSTEPS; s++) {
        const int cur = s & 1;
        const int nxt = cur ^ 1;
        const uint32_t ph   = (uint32_t)((s >> 1) & 1);  // phase parity per barrier object
        const uint32_t bsel = (uint32_t)(cur * 8);       // barrier byte offset

        if (t < 32) {                                    // ---- warp 0: consumer ----
            if (s > 0) bar_sync(3, NT);                  // part_s producers done
            if (t < UNITS) {
                // layer-0 gates: 4x LDS.128 reduction + folded bias (y term included)
                float gi = hsum4(*reinterpret_cast<const float4*>(&part_s[4 * t]))        + b0i;
                float gf = hsum4(*reinterpret_cast<const float4*>(&part_s[4 * (16 + t)])) + b0f;
                float gg = hsum4(*reinterpret_cast<const float4*>(&part_s[4 * (32 + t)])) + b0g;
                float go = hsum4(*reinterpret_cast<const float4*>(&part_s[4 * (48 + t)])) + b0o;
                c0v = sigf(gf) * c0v + sigf(gi) * tanh_f(gg);
                float hn = sigf(go) * tanh_f(c0v);
                // pack pairs and exchange h0(next)
                float hhi = __shfl_down_sync(0x0000ffffu, hn, 1);
                if (t == 0) mbar_expect_tx(barH0a + bsel, HID * 4);
                if ((t & 1) == 0) {
                    uint64_t val = ((uint64_t)__float_as_uint(hhi) << 32)
                                 | (uint64_t)__float_as_uint(hn);
                    uint32_t off = (uint32_t)((nxt * HID + rank * UNITS + t) * 4);
#pragma unroll
                    for (int c = 0; c < CL; c++)
                        st_async64(pbase[c] + off, val, pb0[c] + bsel);
                }
            }
        }

        // overlap: Wh1 @ h1_s while h0 exchange is in flight
        float accB = dot32p(wBp, &bufH1[cur][cbase]);

        mbar_wait_parity(barH0a + bsel, ph);             // h0(next) ready

        // layer-1 partials (transposed)
        part2_s[tp] = dot32p(wAp, &bufH0[nxt][cbase]) + accB;

        if (t < 32) {                                    // ---- warp 0: consumer ----
            bar_sync(2, NT);                             // part2_s producers done
            if (t < UNITS) {
                float gi = hsum4(*reinterpret_cast<const float4*>(&part2_s[4 * t]))        + b1i;
                float gf = hsum4(*reinterpret_cast<const float4*>(&part2_s[4 * (16 + t)])) + b1f;
                float gg = hsum4(*reinterpret_cast<const float4*>(&part2_s[4 * (32 + t)])) + b1g;
                float go = hsum4(*reinterpret_cast<const float4*>(&part2_s[4 * (48 + t)])) + b1o;
                c1v = sigf(gf) * c1v + sigf(gi) * tanh_f(gg);
                float hn = sigf(go) * tanh_f(c1v);
                float hhi = __shfl_down_sync(0x0000ffffu, hn, 1);
                if (t == 0) mbar_expect_tx(barH1a + bsel, HID * 4);
                if ((t & 1) == 0) {
                    uint64_t val = ((uint64_t)__float_as_uint(hhi) << 32)
                                 | (uint64_t)__float_as_uint(hn);
                    uint32_t off = dH1 + (uint32_t)((nxt * HID + rank * UNITS + t) * 4);
#pragma unroll
                    for (int c = 0; c < CL; c++)
                        st_async64(pbase[c] + off, val, pb1[c] + bsel);
                }
            }
        } else {
            bar_arrive(2, NT);                           // producers don't wait
        }

        // overlap: next step's Wh0 @ h0 partial while h1 exchange is in flight
        float p0n = dot32p(w0p, &bufH0[nxt][cbase]);

        mbar_wait_parity(barH1a + bsel, ph);             // h1(next) ready

        // finish next step's layer-0 partials: add folded-fc term over h1(next)
        part_s[tp] = p0n + dot32p(wCp, &bufH1[nxt][cbase]);

        if (t >= 32) bar_arrive(3, NT);                  // publish part_s

        // ---- output y (warp 1, OFF the critical path) ----
        if (t >= 32 && t < 64) {
            const float* hb1 = bufH1[nxt];
            const int l = t - 32;
            float a = fw0 * hb1[l] + fw1 * hb1[32 + l]
                    + fw2 * hb1[64 + l] + fw3 * hb1[96 + l];
            a += __shfl_xor_sync(0xffffffffu, a, 16);
            a += __shfl_xor_sync(0xffffffffu, a, 8);
            a += __shfl_xor_sync(0xffffffffu, a, 4);
            a += __shfl_xor_sync(0xffffffffu, a, 2);
            a += __shfl_xor_sync(0xffffffffu, a, 1);
            if (t == 32 && rank == 0) outp[s] = a + fb;
        }
    }

    // keep smem alive until every peer finished its final remote ops
    asm volatile("barrier.cluster.arrive.aligned;" ::: "memory");
    asm volatile("barrier.cluster.wait.aligned;" ::: "memory");
}

// ---------------- launch ----------------
extern "C" void kernel_launch(void* const* d_in, const int* in_sizes, int n_in,
                              void* d_out, int out_size)
{
    (void)in_sizes; (void)n_in; (void)out_size;
    const float* y0   = (const float*)d_in[0];
    const float* h0   = (const float*)d_in[1];
    const float* c0   = (const float*)d_in[2];
    const float* Wi0  = (const float*)d_in[3];
    const float* Wh0  = (const float*)d_in[4];
    const float* bi0  = (const float*)d_in[5];
    const float* bh0  = (const float*)d_in[6];
    const float* Wi1  = (const float*)d_in[7];
    const float* Wh1  = (const float*)d_in[8];
    const float* bi1  = (const float*)d_in[9];
    const float* bh1  = (const float*)d_in[10];
    const float* fcw  = (const float*)d_in[11];
    const float* fcb  = (const float*)d_in[12];
    float* out = (float*)d_out;

    lstm_decoder_kernel<<<dim3(BATCH * CL, 1, 1), dim3(NT, 1, 1)>>>(
        y0, h0, c0, Wi0, Wh0, bi0, bh0, Wi1, Wh1, bi1, bh1, fcw, fcb, out);
}